// round 10
// baseline (speedup 1.0000x reference)
#include <cuda_runtime.h>
#include <cuda_fp16.h>
#include <cstdint>

// ---------------------------------------------------------------------------
// Problem constants
// ---------------------------------------------------------------------------
#define BB 4
#define SS 8192
#define DD 512
#define MM (BB * SS)          // 32768 rows
#define NG 1536               // fused GEMM cols: [F(512) | interleaved I/H (1024)]
#define KA 512                // A k-extent: fp16(x)
#define KB 512                // B k-extent: fp16(W)

#define TM 128                // CTA tile M
#define TN 128                // CTA tile N
#define KC 64                 // K chunk (128 bytes fp16 per row)
#define NCH (KA / KC)         // 8 chunks
#define NSTAGE 3

#define LCHUNK 64
#define NCHUNK (SS / LCHUNK)  // 128
#define CGRP 8                // carry prefetch group

// ---------------------------------------------------------------------------
// Device scratch
// ---------------------------------------------------------------------------
__device__ __align__(256) __half g_A[(size_t)MM * KA];   // 32 MB
__device__ __align__(256) __half g_B[(size_t)NG * KB];   // 1.5 MB
__device__ float g_bias[NG];
__device__ __align__(256) __half g_f[(size_t)MM * DD];   // 32 MB
__device__ __align__(256) __half g_v[(size_t)MM * DD];   // 32 MB
__device__ float g_chA[BB * NCHUNK * DD];                // 1 MB
__device__ float g_chC[BB * NCHUNK * DD];                // 1 MB
__device__ float g_hin[BB * NCHUNK * DD];                // 1 MB

// ---------------------------------------------------------------------------
// Helpers
// ---------------------------------------------------------------------------
__device__ __forceinline__ float sigmoidf_(float x) { return 1.0f / (1.0f + __expf(-x)); }
__device__ __forceinline__ float gfun_(float x)     { return (x >= 0.0f) ? (x + 0.5f) : sigmoidf_(x); }

__device__ __forceinline__ uint32_t smem_u32(const void* p) {
    uint32_t a;
    asm("{ .reg .u64 t; cvta.to.shared.u64 t, %1; cvt.u32.u64 %0, t; }" : "=r"(a) : "l"(p));
    return a;
}
__device__ __forceinline__ void cpasync16(uint32_t dst, const void* src) {
    asm volatile("cp.async.cg.shared.global [%0], [%1], 16;" :: "r"(dst), "l"(src));
}
__device__ __forceinline__ void ldsm4(uint32_t addr, uint32_t& r0, uint32_t& r1,
                                      uint32_t& r2, uint32_t& r3) {
    asm volatile("ldmatrix.sync.aligned.m8n8.x4.shared.b16 {%0,%1,%2,%3}, [%4];"
                 : "=r"(r0), "=r"(r1), "=r"(r2), "=r"(r3) : "r"(addr));
}
__device__ __forceinline__ void mma16816(float* c, const uint32_t* a, const uint32_t* b) {
    asm volatile(
        "mma.sync.aligned.m16n8k16.row.col.f32.f16.f16.f32 "
        "{%0,%1,%2,%3}, {%4,%5,%6,%7}, {%8,%9}, {%0,%1,%2,%3};"
        : "+f"(c[0]), "+f"(c[1]), "+f"(c[2]), "+f"(c[3])
        : "r"(a[0]), "r"(a[1]), "r"(a[2]), "r"(a[3]), "r"(b[0]), "r"(b[1]));
}

// ---------------------------------------------------------------------------
// Prep A: streaming fp32 -> fp16 cast
// ---------------------------------------------------------------------------
__global__ __launch_bounds__(256) void prep_A(const float* __restrict__ x)
{
    const size_t i = ((size_t)blockIdx.x * 256 + threadIdx.x) * 8;
    float4 v0 = *(const float4*)(x + i);
    float4 v1 = *(const float4*)(x + i + 4);
    __half2 h[4];
    h[0] = __floats2half2_rn(v0.x, v0.y);
    h[1] = __floats2half2_rn(v0.z, v0.w);
    h[2] = __floats2half2_rn(v1.x, v1.y);
    h[3] = __floats2half2_rn(v1.z, v1.w);
    *(uint4*)(g_A + i) = *(uint4*)h;
}

// ---------------------------------------------------------------------------
// Prep B (transposed, coalesced): g_B[n][k] = fp16(W[k][d])
//   n <  512 : gate F, n = d ; n >= 512 : I at 512+2d, H at 513+2d
// ---------------------------------------------------------------------------
__global__ __launch_bounds__(256) void prep_Bt(
    const float* __restrict__ Wf, const float* __restrict__ Wi,
    const float* __restrict__ Wh)
{
    __shared__ float tile[3][32][33];
    const int d0 = blockIdx.x * 32, k0 = blockIdx.y * 32;
    const int tx = threadIdx.x, ty = threadIdx.y;
    const float* Ws[3] = {Wf, Wi, Wh};
#pragma unroll
    for (int g = 0; g < 3; g++)
#pragma unroll
        for (int i = 0; i < 4; i++) {
            const int k = k0 + ty + i * 8;
            tile[g][ty + i * 8][tx] = Ws[g][(size_t)k * DD + d0 + tx];
        }
    __syncthreads();
#pragma unroll
    for (int i = 0; i < 4; i++) {
        const int r = ty + i * 8;       // local d
        const int d = d0 + r;
        g_B[(size_t)d * KB + k0 + tx]             = __float2half_rn(tile[0][tx][r]);
        g_B[(size_t)(512 + 2 * d) * KB + k0 + tx] = __float2half_rn(tile[1][tx][r]);
        g_B[(size_t)(513 + 2 * d) * KB + k0 + tx] = __float2half_rn(tile[2][tx][r]);
    }
}

__global__ __launch_bounds__(256) void prep_bias(
    const float* __restrict__ bf, const float* __restrict__ bi,
    const float* __restrict__ bh)
{
    const int d = blockIdx.x * 256 + threadIdx.x;   // 0..511
    g_bias[d]           = bf[d];
    g_bias[512 + 2 * d] = bi[d];
    g_bias[513 + 2 * d] = bh[d];
}

// ---------------------------------------------------------------------------
// HMMA GEMM + fused activation epilogue (fp16 outputs).
// CTA 128x128, 4 warps, warp tile 64x64 (2m x 2n), 3-stage cp.async pipeline.
// grid = (NG/TN, MM/TM), block = 128
// ---------------------------------------------------------------------------
__global__ __launch_bounds__(128, 2) void gemm_tc()
{
    extern __shared__ __align__(128) char smem_raw[];
    const uint32_t sbase = smem_u32(smem_raw);

    const int tid  = threadIdx.x;
    const int lane = tid & 31;
    const int wid  = tid >> 5;            // 0..3
    const int wm   = wid >> 1;            // 0..1  (m)
    const int wn   = wid & 1;             // 0..1  (n)
    const int m0 = blockIdx.y * TM;
    const int n0 = blockIdx.x * TN;

    const int quad = lane >> 3;
    const int lrow = lane & 7;

    const __half* gA = g_A + (size_t)m0 * KA;
    const __half* gB = g_B + (size_t)n0 * KB;

    auto load_chunk = [&](int c, int s) {
        const uint32_t aB = sbase + (uint32_t)s * 32768u;
        const uint32_t bB = aB + 16384u;
        const int koff = c * KC;
#pragma unroll
        for (int j = 0; j < 8; j++) {
            const int flat = tid + j * 128;       // 0..1023
            const int r  = flat >> 3;             // row 0..127
            const int sg = flat & 7;              // 16B segment 0..7
            const uint32_t sw = ((uint32_t)(sg ^ (r & 7))) << 4;
            cpasync16(aB + (uint32_t)r * 128u + sw, gA + (size_t)r * KA + koff + sg * 8);
            cpasync16(bB + (uint32_t)r * 128u + sw, gB + (size_t)r * KB + koff + sg * 8);
        }
        asm volatile("cp.async.commit_group;" ::: "memory");
    };

    float acc[4][8][4];
#pragma unroll
    for (int i = 0; i < 4; i++)
#pragma unroll
        for (int j = 0; j < 8; j++)
#pragma unroll
            for (int q = 0; q < 4; q++) acc[i][j][q] = 0.0f;

    load_chunk(0, 0);
    load_chunk(1, 1);

#pragma unroll 1
    for (int c = 0; c < NCH; c++) {
        const int s = c % 3;
        asm volatile("cp.async.wait_group 1;" ::: "memory");
        __syncthreads();
        if (c + 2 < NCH) load_chunk(c + 2, (c + 2) % 3);
        else             asm volatile("cp.async.commit_group;" ::: "memory");

        const uint32_t aB = sbase + (uint32_t)s * 32768u;
        const uint32_t bB = aB + 16384u;

#pragma unroll
        for (int ks = 0; ks < 4; ks++) {
            uint32_t afr[4][4];
#pragma unroll
            for (int mt = 0; mt < 4; mt++) {
                const int row = wm * 64 + mt * 16 + (quad & 1) * 8 + lrow;
                const int seg = (ks * 2) + (quad >> 1);
                const uint32_t addr = aB + (uint32_t)row * 128u +
                                      ((uint32_t)(seg ^ (row & 7)) << 4);
                ldsm4(addr, afr[mt][0], afr[mt][1], afr[mt][2], afr[mt][3]);
            }
            uint32_t bfr[8][2];
#pragma unroll
            for (int np = 0; np < 4; np++) {
                const int nrow = wn * 64 + np * 16 + (quad >> 1) * 8 + lrow;
                const int seg = (ks * 2) + (quad & 1);
                const uint32_t addr = bB + (uint32_t)nrow * 128u +
                                      ((uint32_t)(seg ^ (nrow & 7)) << 4);
                ldsm4(addr, bfr[np * 2][0], bfr[np * 2][1],
                            bfr[np * 2 + 1][0], bfr[np * 2 + 1][1]);
            }
#pragma unroll
            for (int mt = 0; mt < 4; mt++)
#pragma unroll
                for (int nt = 0; nt < 8; nt++)
                    mma16816(acc[mt][nt], afr[mt], bfr[nt]);
        }
    }
    __syncthreads();

    if (n0 < 512) {
        // F gate: f = sigmoid(k + b), store half2 pairs directly (R8 layout)
#pragma unroll
        for (int mt = 0; mt < 4; mt++) {
            const int mr = m0 + wm * 64 + mt * 16 + (lane >> 2);
#pragma unroll
            for (int nt = 0; nt < 8; nt++) {
                const int n = n0 + wn * 64 + nt * 8 + (lane & 3) * 2;
                const float bx = __ldg(&g_bias[n]);
                const float by = __ldg(&g_bias[n + 1]);
                __half2 p0 = __floats2half2_rn(sigmoidf_(acc[mt][nt][0] + bx),
                                               sigmoidf_(acc[mt][nt][1] + by));
                __half2 p1 = __floats2half2_rn(sigmoidf_(acc[mt][nt][2] + bx),
                                               sigmoidf_(acc[mt][nt][3] + by));
                *(__half2*)(g_f + (size_t)mr * DD + n)       = p0;
                *(__half2*)(g_f + (size_t)(mr + 8) * DD + n) = p1;
            }
        }
    } else {
        // I/H interleaved: fragment cols (2j, 2j+1) = (I_d, H_d)
        // v = sigmoid(kI + bI) * g(kH + bH). Stage fp32 in smem, store fp16.
        float* vbuf = (float*)smem_raw;     // [128][68] floats = 34816 B
        const int dloc_base = wn * 32;
#pragma unroll
        for (int mt = 0; mt < 4; mt++) {
            const int rloc = wm * 64 + mt * 16 + (lane >> 2);
#pragma unroll
            for (int nt = 0; nt < 8; nt++) {
                const int n = n0 + wn * 64 + nt * 8 + (lane & 3) * 2;
                const float bi_ = __ldg(&g_bias[n]);
                const float bh_ = __ldg(&g_bias[n + 1]);
                const int dloc = dloc_base + nt * 4 + (lane & 3);
                vbuf[rloc * 68 + dloc] =
                    sigmoidf_(acc[mt][nt][0] + bi_) * gfun_(acc[mt][nt][1] + bh_);
                vbuf[(rloc + 8) * 68 + dloc] =
                    sigmoidf_(acc[mt][nt][2] + bi_) * gfun_(acc[mt][nt][3] + bh_);
            }
        }
        __syncthreads();
        const int dbase = (n0 - 512) >> 1;   // global d of local col 0
#pragma unroll
        for (int j = 0; j < 16; j++) {
            const int flat = tid + j * 128;  // 0..2047 float4 units
            const int r  = flat >> 4;        // row 0..127
            const int f4 = flat & 15;        // 0..15
            float4 val = *(float4*)(vbuf + r * 68 + f4 * 4);
            __half2 h01 = __floats2half2_rn(val.x, val.y);
            __half2 h23 = __floats2half2_rn(val.z, val.w);
            uint2 pk;
            pk.x = *(uint32_t*)&h01;
            pk.y = *(uint32_t*)&h23;
            *(uint2*)(g_v + (size_t)(m0 + r) * DD + dbase + f4 * 4) = pk;
        }
    }
}

// ---------------------------------------------------------------------------
// Scan pass 1: per-chunk affine reduction. block=256 (2 channels/thread)
// grid=(NCHUNK, BB)
// ---------------------------------------------------------------------------
__global__ __launch_bounds__(256) void scan_chunks_kernel()
{
    const int b = blockIdx.y, c = blockIdx.x, t = threadIdx.x;
    const __half2* F = (const __half2*)g_f;
    const __half2* V = (const __half2*)g_v;
    size_t idx = (size_t)(b * SS + c * LCHUNK) * (DD / 2) + t;
    float2 A = {1.0f, 1.0f}, C = {0.0f, 0.0f};
#pragma unroll 4
    for (int s = 0; s < LCHUNK; s++) {
        float2 f = __half22float2(F[idx]);
        float2 v = __half22float2(V[idx]);
        A.x *= f.x;  A.y *= f.y;
        C.x = fmaf(f.x, C.x, v.x);
        C.y = fmaf(f.y, C.y, v.y);
        idx += DD / 2;
    }
    const int o = (b * NCHUNK + c) * DD + 2 * t;
    *(float2*)(g_chA + o) = A;
    *(float2*)(g_chC + o) = C;
}

// ---------------------------------------------------------------------------
// Scan pass 2: serial carry, latency-hidden via group double-buffering.
// grid=BB, block=256
// ---------------------------------------------------------------------------
__global__ __launch_bounds__(256) void scan_carry_kernel(const float* __restrict__ pre_h)
{
    const int b = blockIdx.x, t = threadIdx.x;
    float2 h;
    h.x = gfun_(pre_h[b * DD + 2 * t]);
    h.y = gfun_(pre_h[b * DD + 2 * t + 1]);

    const int base = b * NCHUNK * DD + 2 * t;   // element offset of chunk 0

    float2 Abuf[2][CGRP], Cbuf[2][CGRP];
#pragma unroll
    for (int j = 0; j < CGRP; j++) {
        Abuf[0][j] = *(const float2*)(g_chA + base + j * DD);
        Cbuf[0][j] = *(const float2*)(g_chC + base + j * DD);
    }

#pragma unroll 1
    for (int g = 0; g < NCHUNK / CGRP; g++) {
        const int cur = g & 1, nxt = cur ^ 1;
        if (g + 1 < NCHUNK / CGRP) {
            const int nb = base + (g + 1) * CGRP * DD;
#pragma unroll
            for (int j = 0; j < CGRP; j++) {
                Abuf[nxt][j] = *(const float2*)(g_chA + nb + j * DD);
                Cbuf[nxt][j] = *(const float2*)(g_chC + nb + j * DD);
            }
        }
        const int cb = base + g * CGRP * DD;
#pragma unroll
        for (int j = 0; j < CGRP; j++) {
            *(float2*)(g_hin + cb + j * DD) = h;
            h.x = fmaf(Abuf[cur][j].x, h.x, Cbuf[cur][j].x);
            h.y = fmaf(Abuf[cur][j].y, h.y, Cbuf[cur][j].y);
        }
    }
}

// ---------------------------------------------------------------------------
// Scan pass 3: replay chunks, write fp32 output.
// grid=(NCHUNK, BB), block=256
// ---------------------------------------------------------------------------
__global__ __launch_bounds__(256) void scan_apply_kernel(float* __restrict__ out)
{
    const int b = blockIdx.y, c = blockIdx.x, t = threadIdx.x;
    const __half2* F = (const __half2*)g_f;
    const __half2* V = (const __half2*)g_v;
    float2 h = *(const float2*)(g_hin + (b * NCHUNK + c) * DD + 2 * t);
    size_t idx = (size_t)(b * SS + c * LCHUNK) * (DD / 2) + t;
#pragma unroll 4
    for (int s = 0; s < LCHUNK; s++) {
        float2 f = __half22float2(F[idx]);
        float2 v = __half22float2(V[idx]);
        h.x = fmaf(f.x, h.x, v.x);
        h.y = fmaf(f.y, h.y, v.y);
        *(float2*)(out + idx * 2) = h;
        idx += DD / 2;
    }
}

// ---------------------------------------------------------------------------
extern "C" void kernel_launch(void* const* d_in, const int* in_sizes, int n_in,
                              void* d_out, int out_size)
{
    const float* x     = (const float*)d_in[0];
    const float* pre_h = (const float*)d_in[1];
    const float* Wf    = (const float*)d_in[2];
    const float* bf    = (const float*)d_in[3];
    const float* Wi    = (const float*)d_in[4];
    const float* bi    = (const float*)d_in[5];
    const float* Wh    = (const float*)d_in[6];
    const float* bh    = (const float*)d_in[7];
    float* out = (float*)d_out;

    static bool attr_set = false;
    if (!attr_set) {
        cudaFuncSetAttribute(gemm_tc, cudaFuncAttributeMaxDynamicSharedMemorySize,
                             NSTAGE * 32768);
        attr_set = true;
    }

    prep_A<<<(MM * DD) / (256 * 8), 256>>>(x);
    prep_Bt<<<dim3(16, 16), dim3(32, 8)>>>(Wf, Wi, Wh);
    prep_bias<<<2, 256>>>(bf, bi, bh);

    gemm_tc<<<dim3(NG / TN, MM / TM), 128, NSTAGE * 32768>>>();

    scan_chunks_kernel<<<dim3(NCHUNK, BB), 256>>>();
    scan_carry_kernel<<<BB, 256>>>(pre_h);
    scan_apply_kernel<<<dim3(NCHUNK, BB), 256>>>(out);
}

// round 11
// speedup vs baseline: 1.2904x; 1.2904x over previous
#include <cuda_runtime.h>
#include <cuda_fp16.h>
#include <cstdint>

// ---------------------------------------------------------------------------
// Problem constants
// ---------------------------------------------------------------------------
#define BB 4
#define SS 8192
#define DD 512
#define MM (BB * SS)          // 32768 rows
#define NG 1536               // fused GEMM cols: [F(512) | interleaved I/H (1024)]
#define KA 512                // A k-extent: fp16(x)
#define KB 512                // B k-extent: fp16(W)

#define TM 128                // CTA tile M
#define TN 128                // CTA tile N
#define KC 64                 // K chunk (128 bytes fp16 per row)
#define NCH (KA / KC)         // 8 chunks
#define NSTAGE 3

#define LCHUNK 64
#define NCHUNK (SS / LCHUNK)  // 128
#define CGRP 8                // carry prefetch group

// ---------------------------------------------------------------------------
// Device scratch
// ---------------------------------------------------------------------------
__device__ __align__(256) __half g_A[(size_t)MM * KA];   // 32 MB
__device__ __align__(256) __half g_B[(size_t)NG * KB];   // 1.5 MB
__device__ float g_bias[NG];
__device__ __align__(256) __half g_f[(size_t)MM * DD];   // 32 MB
__device__ __align__(256) __half g_v[(size_t)MM * DD];   // 32 MB
__device__ float g_chA[BB * NCHUNK * DD];                // 1 MB
__device__ float g_chC[BB * NCHUNK * DD];                // 1 MB
__device__ float g_hin[BB * NCHUNK * DD];                // 1 MB

// ---------------------------------------------------------------------------
// Helpers
// ---------------------------------------------------------------------------
__device__ __forceinline__ float sigmoidf_(float x) { return 1.0f / (1.0f + __expf(-x)); }
__device__ __forceinline__ float gfun_(float x)     { return (x >= 0.0f) ? (x + 0.5f) : sigmoidf_(x); }

__device__ __forceinline__ uint32_t smem_u32(const void* p) {
    uint32_t a;
    asm("{ .reg .u64 t; cvta.to.shared.u64 t, %1; cvt.u32.u64 %0, t; }" : "=r"(a) : "l"(p));
    return a;
}
__device__ __forceinline__ void cpasync16(uint32_t dst, const void* src) {
    asm volatile("cp.async.cg.shared.global [%0], [%1], 16;" :: "r"(dst), "l"(src));
}
__device__ __forceinline__ void ldsm4(uint32_t addr, uint32_t& r0, uint32_t& r1,
                                      uint32_t& r2, uint32_t& r3) {
    asm volatile("ldmatrix.sync.aligned.m8n8.x4.shared.b16 {%0,%1,%2,%3}, [%4];"
                 : "=r"(r0), "=r"(r1), "=r"(r2), "=r"(r3) : "r"(addr));
}
__device__ __forceinline__ void mma16816(float* c, const uint32_t* a, const uint32_t* b) {
    asm volatile(
        "mma.sync.aligned.m16n8k16.row.col.f32.f16.f16.f32 "
        "{%0,%1,%2,%3}, {%4,%5,%6,%7}, {%8,%9}, {%0,%1,%2,%3};"
        : "+f"(c[0]), "+f"(c[1]), "+f"(c[2]), "+f"(c[3])
        : "r"(a[0]), "r"(a[1]), "r"(a[2]), "r"(a[3]), "r"(b[0]), "r"(b[1]));
}

// ---------------------------------------------------------------------------
// Prep A: streaming fp32 -> fp16 cast
// ---------------------------------------------------------------------------
__global__ __launch_bounds__(256) void prep_A(const float* __restrict__ x)
{
    const size_t i = ((size_t)blockIdx.x * 256 + threadIdx.x) * 8;
    float4 v0 = *(const float4*)(x + i);
    float4 v1 = *(const float4*)(x + i + 4);
    __half2 h[4];
    h[0] = __floats2half2_rn(v0.x, v0.y);
    h[1] = __floats2half2_rn(v0.z, v0.w);
    h[2] = __floats2half2_rn(v1.x, v1.y);
    h[3] = __floats2half2_rn(v1.z, v1.w);
    *(uint4*)(g_A + i) = *(uint4*)h;
}

// ---------------------------------------------------------------------------
// Prep B (transposed, coalesced) + bias: g_B[n][k] = fp16(W[k][d])
//   n <  512 : gate F, n = d ; n >= 512 : I at 512+2d, H at 513+2d
// ---------------------------------------------------------------------------
__global__ __launch_bounds__(256) void prep_Bt(
    const float* __restrict__ Wf, const float* __restrict__ Wi,
    const float* __restrict__ Wh,
    const float* __restrict__ bf, const float* __restrict__ bi,
    const float* __restrict__ bh)
{
    __shared__ float tile[3][32][33];
    const int d0 = blockIdx.x * 32, k0 = blockIdx.y * 32;
    const int tx = threadIdx.x, ty = threadIdx.y;
    const float* Ws[3] = {Wf, Wi, Wh};
#pragma unroll
    for (int g = 0; g < 3; g++)
#pragma unroll
        for (int i = 0; i < 4; i++) {
            const int k = k0 + ty + i * 8;
            tile[g][ty + i * 8][tx] = Ws[g][(size_t)k * DD + d0 + tx];
        }
    if (blockIdx.y == 0 && ty == 0) {
        const int d = d0 + tx;
        g_bias[d]           = bf[d];
        g_bias[512 + 2 * d] = bi[d];
        g_bias[513 + 2 * d] = bh[d];
    }
    __syncthreads();
#pragma unroll
    for (int i = 0; i < 4; i++) {
        const int r = ty + i * 8;       // local d
        const int d = d0 + r;
        g_B[(size_t)d * KB + k0 + tx]             = __float2half_rn(tile[0][tx][r]);
        g_B[(size_t)(512 + 2 * d) * KB + k0 + tx] = __float2half_rn(tile[1][tx][r]);
        g_B[(size_t)(513 + 2 * d) * KB + k0 + tx] = __float2half_rn(tile[2][tx][r]);
    }
}

// ---------------------------------------------------------------------------
// HMMA GEMM + fused activation epilogue (fp16 outputs).
// CTA 128x128, warp 32x64, KC=64 chunks, 3-stage cp.async pipeline.
// Fully-unrolled chunk loop (stage indices compile-time).
// grid = (NG/TN, MM/TM), block = 256
// ---------------------------------------------------------------------------
__global__ __launch_bounds__(256, 2) void gemm_tc()
{
    extern __shared__ __align__(128) char smem_raw[];
    const uint32_t sbase = smem_u32(smem_raw);

    const int tid  = threadIdx.x;
    const int lane = tid & 31;
    const int wid  = tid >> 5;
    const int wm   = wid >> 1;            // 0..3  (m)
    const int wn   = wid & 1;             // 0..1  (n)
    const int m0 = blockIdx.y * TM;
    const int n0 = blockIdx.x * TN;

    const int quad = lane >> 3;
    const int lrow = lane & 7;

    const __half* gA = g_A + (size_t)m0 * KA;
    const __half* gB = g_B + (size_t)n0 * KB;

    auto load_chunk = [&](int c, int s) {
        const uint32_t aB = sbase + (uint32_t)s * 32768u;
        const uint32_t bB = aB + 16384u;
        const int koff = c * KC;
#pragma unroll
        for (int j = 0; j < 4; j++) {
            const int flat = tid + j * 256;       // 0..1023
            const int r  = flat >> 3;             // row 0..127
            const int sg = flat & 7;              // 16B segment 0..7
            const uint32_t sw = ((uint32_t)(sg ^ (r & 7))) << 4;
            cpasync16(aB + (uint32_t)r * 128u + sw, gA + (size_t)r * KA + koff + sg * 8);
            cpasync16(bB + (uint32_t)r * 128u + sw, gB + (size_t)r * KB + koff + sg * 8);
        }
        asm volatile("cp.async.commit_group;" ::: "memory");
    };

    float acc[2][8][4];
#pragma unroll
    for (int i = 0; i < 2; i++)
#pragma unroll
        for (int j = 0; j < 8; j++)
#pragma unroll
            for (int q = 0; q < 4; q++) acc[i][j][q] = 0.0f;

    load_chunk(0, 0);
    load_chunk(1, 1);

#pragma unroll
    for (int c = 0; c < NCH; c++) {
        const int s = c % 3;
        asm volatile("cp.async.wait_group 1;" ::: "memory");
        __syncthreads();
        if (c + 2 < NCH) load_chunk(c + 2, (c + 2) % 3);
        else             asm volatile("cp.async.commit_group;" ::: "memory");

        const uint32_t aB = sbase + (uint32_t)s * 32768u;
        const uint32_t bB = aB + 16384u;

#pragma unroll
        for (int ks = 0; ks < 4; ks++) {
            uint32_t afr[2][4];
#pragma unroll
            for (int mt = 0; mt < 2; mt++) {
                const int row = wm * 32 + mt * 16 + (quad & 1) * 8 + lrow;
                const int seg = (ks * 2) + (quad >> 1);
                const uint32_t addr = aB + (uint32_t)row * 128u +
                                      ((uint32_t)(seg ^ (row & 7)) << 4);
                ldsm4(addr, afr[mt][0], afr[mt][1], afr[mt][2], afr[mt][3]);
            }
            uint32_t bfr[8][2];
#pragma unroll
            for (int np = 0; np < 4; np++) {
                const int nrow = wn * 64 + np * 16 + (quad >> 1) * 8 + lrow;
                const int seg = (ks * 2) + (quad & 1);
                const uint32_t addr = bB + (uint32_t)nrow * 128u +
                                      ((uint32_t)(seg ^ (nrow & 7)) << 4);
                ldsm4(addr, bfr[np * 2][0], bfr[np * 2][1],
                            bfr[np * 2 + 1][0], bfr[np * 2 + 1][1]);
            }
#pragma unroll
            for (int mt = 0; mt < 2; mt++)
#pragma unroll
                for (int nt = 0; nt < 8; nt++)
                    mma16816(acc[mt][nt], afr[mt], bfr[nt]);
        }
    }
    __syncthreads();

    if (n0 < 512) {
        // F gate: f = sigmoid(k + b), store half2 pairs
#pragma unroll
        for (int mt = 0; mt < 2; mt++) {
            const int mr = m0 + wm * 32 + mt * 16 + (lane >> 2);
#pragma unroll
            for (int nt = 0; nt < 8; nt++) {
                const int n = n0 + wn * 64 + nt * 8 + (lane & 3) * 2;
                const float bx = __ldg(&g_bias[n]);
                const float by = __ldg(&g_bias[n + 1]);
                __half2 p0 = __floats2half2_rn(sigmoidf_(acc[mt][nt][0] + bx),
                                               sigmoidf_(acc[mt][nt][1] + by));
                __half2 p1 = __floats2half2_rn(sigmoidf_(acc[mt][nt][2] + bx),
                                               sigmoidf_(acc[mt][nt][3] + by));
                *(__half2*)(g_f + (size_t)mr * DD + n)       = p0;
                *(__half2*)(g_f + (size_t)(mr + 8) * DD + n) = p1;
            }
        }
    } else {
        // I/H interleaved: fragment cols (2j, 2j+1) = (I_d, H_d)
        // v = sigmoid(kI + bI) * g(kH + bH). Stage fp32 in smem, store fp16.
        float* vbuf = (float*)smem_raw;     // [128][68] floats = 34816 B
        const int dloc_base = wn * 32;
#pragma unroll
        for (int mt = 0; mt < 2; mt++) {
            const int rloc = wm * 32 + mt * 16 + (lane >> 2);
#pragma unroll
            for (int nt = 0; nt < 8; nt++) {
                const int n = n0 + wn * 64 + nt * 8 + (lane & 3) * 2;
                const float bi_ = __ldg(&g_bias[n]);
                const float bh_ = __ldg(&g_bias[n + 1]);
                const int dloc = dloc_base + nt * 4 + (lane & 3);
                vbuf[rloc * 68 + dloc] =
                    sigmoidf_(acc[mt][nt][0] + bi_) * gfun_(acc[mt][nt][1] + bh_);
                vbuf[(rloc + 8) * 68 + dloc] =
                    sigmoidf_(acc[mt][nt][2] + bi_) * gfun_(acc[mt][nt][3] + bh_);
            }
        }
        __syncthreads();
        const int dbase = (n0 - 512) >> 1;   // global d of local col 0
#pragma unroll
        for (int j = 0; j < 8; j++) {
            const int flat = tid + j * 256;  // 0..2047 float4 units
            const int r  = flat >> 4;        // row 0..127
            const int f4 = flat & 15;        // 0..15
            float4 val = *(float4*)(vbuf + r * 68 + f4 * 4);
            __half2 h01 = __floats2half2_rn(val.x, val.y);
            __half2 h23 = __floats2half2_rn(val.z, val.w);
            uint2 pk;
            pk.x = *(uint32_t*)&h01;
            pk.y = *(uint32_t*)&h23;
            *(uint2*)(g_v + (size_t)(m0 + r) * DD + dbase + f4 * 4) = pk;
        }
    }
}

// ---------------------------------------------------------------------------
// Scan pass 1: per-chunk affine reduction. block=256 (2 channels/thread)
// grid=(NCHUNK, BB)
// ---------------------------------------------------------------------------
__global__ __launch_bounds__(256) void scan_chunks_kernel()
{
    const int b = blockIdx.y, c = blockIdx.x, t = threadIdx.x;
    const __half2* F = (const __half2*)g_f;
    const __half2* V = (const __half2*)g_v;
    size_t idx = (size_t)(b * SS + c * LCHUNK) * (DD / 2) + t;
    float2 A = {1.0f, 1.0f}, C = {0.0f, 0.0f};
#pragma unroll 4
    for (int s = 0; s < LCHUNK; s++) {
        float2 f = __half22float2(F[idx]);
        float2 v = __half22float2(V[idx]);
        A.x *= f.x;  A.y *= f.y;
        C.x = fmaf(f.x, C.x, v.x);
        C.y = fmaf(f.y, C.y, v.y);
        idx += DD / 2;
    }
    const int o = (b * NCHUNK + c) * DD + 2 * t;
    *(float2*)(g_chA + o) = A;
    *(float2*)(g_chC + o) = C;
}

// ---------------------------------------------------------------------------
// Scan pass 2: serial carry, latency-hidden via group double-buffering.
// grid=BB, block=256
// ---------------------------------------------------------------------------
__global__ __launch_bounds__(256) void scan_carry_kernel(const float* __restrict__ pre_h)
{
    const int b = blockIdx.x, t = threadIdx.x;
    float2 h;
    h.x = gfun_(pre_h[b * DD + 2 * t]);
    h.y = gfun_(pre_h[b * DD + 2 * t + 1]);

    const int base = b * NCHUNK * DD + 2 * t;   // element offset of chunk 0

    float2 Abuf[2][CGRP], Cbuf[2][CGRP];
#pragma unroll
    for (int j = 0; j < CGRP; j++) {
        Abuf[0][j] = *(const float2*)(g_chA + base + j * DD);
        Cbuf[0][j] = *(const float2*)(g_chC + base + j * DD);
    }

#pragma unroll 1
    for (int g = 0; g < NCHUNK / CGRP; g++) {
        const int cur = g & 1, nxt = cur ^ 1;
        if (g + 1 < NCHUNK / CGRP) {
            const int nb = base + (g + 1) * CGRP * DD;
#pragma unroll
            for (int j = 0; j < CGRP; j++) {
                Abuf[nxt][j] = *(const float2*)(g_chA + nb + j * DD);
                Cbuf[nxt][j] = *(const float2*)(g_chC + nb + j * DD);
            }
        }
        const int cb = base + g * CGRP * DD;
#pragma unroll
        for (int j = 0; j < CGRP; j++) {
            *(float2*)(g_hin + cb + j * DD) = h;
            h.x = fmaf(Abuf[cur][j].x, h.x, Cbuf[cur][j].x);
            h.y = fmaf(Abuf[cur][j].y, h.y, Cbuf[cur][j].y);
        }
    }
}

// ---------------------------------------------------------------------------
// Scan pass 3: replay chunks, write fp32 output.
// grid=(NCHUNK, BB), block=256
// ---------------------------------------------------------------------------
__global__ __launch_bounds__(256) void scan_apply_kernel(float* __restrict__ out)
{
    const int b = blockIdx.y, c = blockIdx.x, t = threadIdx.x;
    const __half2* F = (const __half2*)g_f;
    const __half2* V = (const __half2*)g_v;
    float2 h = *(const float2*)(g_hin + (b * NCHUNK + c) * DD + 2 * t);
    size_t idx = (size_t)(b * SS + c * LCHUNK) * (DD / 2) + t;
#pragma unroll 4
    for (int s = 0; s < LCHUNK; s++) {
        float2 f = __half22float2(F[idx]);
        float2 v = __half22float2(V[idx]);
        h.x = fmaf(f.x, h.x, v.x);
        h.y = fmaf(f.y, h.y, v.y);
        *(float2*)(out + idx * 2) = h;
        idx += DD / 2;
    }
}

// ---------------------------------------------------------------------------
extern "C" void kernel_launch(void* const* d_in, const int* in_sizes, int n_in,
                              void* d_out, int out_size)
{
    const float* x     = (const float*)d_in[0];
    const float* pre_h = (const float*)d_in[1];
    const float* Wf    = (const float*)d_in[2];
    const float* bf    = (const float*)d_in[3];
    const float* Wi    = (const float*)d_in[4];
    const float* bi    = (const float*)d_in[5];
    const float* Wh    = (const float*)d_in[6];
    const float* bh    = (const float*)d_in[7];
    float* out = (float*)d_out;

    static bool attr_set = false;
    if (!attr_set) {
        cudaFuncSetAttribute(gemm_tc, cudaFuncAttributeMaxDynamicSharedMemorySize,
                             NSTAGE * 32768);
        attr_set = true;
    }

    prep_A<<<(MM * DD) / (256 * 8), 256>>>(x);
    prep_Bt<<<dim3(16, 16), dim3(32, 8)>>>(Wf, Wi, Wh, bf, bi, bh);

    gemm_tc<<<dim3(NG / TN, MM / TM), 256, NSTAGE * 32768>>>();

    scan_chunks_kernel<<<dim3(NCHUNK, BB), 256>>>();
    scan_carry_kernel<<<BB, 256>>>(pre_h);
    scan_apply_kernel<<<dim3(NCHUNK, BB), 256>>>(out);
}

// round 12
// speedup vs baseline: 1.3141x; 1.0184x over previous
#include <cuda_runtime.h>
#include <cuda_fp16.h>
#include <cstdint>

// ---------------------------------------------------------------------------
// Problem constants
// ---------------------------------------------------------------------------
#define BB 4
#define SS 8192
#define DD 512
#define MM (BB * SS)          // 32768 rows
#define NG 1536               // fused GEMM cols: [F(512) | interleaved I/H (1024)]
#define KA 512                // A k-extent: fp16(x)
#define KB 512                // B k-extent: fp16(W)

#define TM 128                // CTA tile M
#define TN 128                // CTA tile N
#define KC 64                 // K chunk (128 bytes fp16 per row)
#define NCH (KA / KC)         // 8 chunks
#define NSTAGE 3

#define LCHUNK 64
#define NCHUNK (SS / LCHUNK)  // 128
#define CGRP 8                // carry prefetch group
#define SGRP 8                // scan load-batch group

// ---------------------------------------------------------------------------
// Device scratch
// ---------------------------------------------------------------------------
__device__ __align__(256) __half g_A[(size_t)MM * KA];   // 32 MB
__device__ __align__(256) __half g_B[(size_t)NG * KB];   // 1.5 MB
__device__ float g_bias[NG];
__device__ __align__(256) __half g_f[(size_t)MM * DD];   // 32 MB
__device__ __align__(256) __half g_v[(size_t)MM * DD];   // 32 MB
__device__ float g_chA[BB * NCHUNK * DD];                // 1 MB
__device__ float g_chC[BB * NCHUNK * DD];                // 1 MB
__device__ float g_hin[BB * NCHUNK * DD];                // 1 MB

// ---------------------------------------------------------------------------
// Helpers
// ---------------------------------------------------------------------------
__device__ __forceinline__ float sigmoidf_(float x) { return 1.0f / (1.0f + __expf(-x)); }
__device__ __forceinline__ float gfun_(float x)     { return (x >= 0.0f) ? (x + 0.5f) : sigmoidf_(x); }

__device__ __forceinline__ uint32_t smem_u32(const void* p) {
    uint32_t a;
    asm("{ .reg .u64 t; cvta.to.shared.u64 t, %1; cvt.u32.u64 %0, t; }" : "=r"(a) : "l"(p));
    return a;
}
__device__ __forceinline__ void cpasync16(uint32_t dst, const void* src) {
    asm volatile("cp.async.cg.shared.global [%0], [%1], 16;" :: "r"(dst), "l"(src));
}
__device__ __forceinline__ void ldsm4(uint32_t addr, uint32_t& r0, uint32_t& r1,
                                      uint32_t& r2, uint32_t& r3) {
    asm volatile("ldmatrix.sync.aligned.m8n8.x4.shared.b16 {%0,%1,%2,%3}, [%4];"
                 : "=r"(r0), "=r"(r1), "=r"(r2), "=r"(r3) : "r"(addr));
}
__device__ __forceinline__ void mma16816(float* c, const uint32_t* a, const uint32_t* b) {
    asm volatile(
        "mma.sync.aligned.m16n8k16.row.col.f32.f16.f16.f32 "
        "{%0,%1,%2,%3}, {%4,%5,%6,%7}, {%8,%9}, {%0,%1,%2,%3};"
        : "+f"(c[0]), "+f"(c[1]), "+f"(c[2]), "+f"(c[3])
        : "r"(a[0]), "r"(a[1]), "r"(a[2]), "r"(a[3]), "r"(b[0]), "r"(b[1]));
}

// ---------------------------------------------------------------------------
// Prep A: streaming fp32 -> fp16 cast
// ---------------------------------------------------------------------------
__global__ __launch_bounds__(256) void prep_A(const float* __restrict__ x)
{
    const size_t i = ((size_t)blockIdx.x * 256 + threadIdx.x) * 8;
    float4 v0 = *(const float4*)(x + i);
    float4 v1 = *(const float4*)(x + i + 4);
    __half2 h[4];
    h[0] = __floats2half2_rn(v0.x, v0.y);
    h[1] = __floats2half2_rn(v0.z, v0.w);
    h[2] = __floats2half2_rn(v1.x, v1.y);
    h[3] = __floats2half2_rn(v1.z, v1.w);
    *(uint4*)(g_A + i) = *(uint4*)h;
}

// ---------------------------------------------------------------------------
// Prep B (transposed, coalesced) + bias: g_B[n][k] = fp16(W[k][d])
//   n <  512 : gate F, n = d ; n >= 512 : I at 512+2d, H at 513+2d
// ---------------------------------------------------------------------------
__global__ __launch_bounds__(256) void prep_Bt(
    const float* __restrict__ Wf, const float* __restrict__ Wi,
    const float* __restrict__ Wh,
    const float* __restrict__ bf, const float* __restrict__ bi,
    const float* __restrict__ bh)
{
    __shared__ float tile[3][32][33];
    const int d0 = blockIdx.x * 32, k0 = blockIdx.y * 32;
    const int tx = threadIdx.x, ty = threadIdx.y;
    const float* Ws[3] = {Wf, Wi, Wh};
#pragma unroll
    for (int g = 0; g < 3; g++)
#pragma unroll
        for (int i = 0; i < 4; i++) {
            const int k = k0 + ty + i * 8;
            tile[g][ty + i * 8][tx] = Ws[g][(size_t)k * DD + d0 + tx];
        }
    if (blockIdx.y == 0 && ty == 0) {
        const int d = d0 + tx;
        g_bias[d]           = bf[d];
        g_bias[512 + 2 * d] = bi[d];
        g_bias[513 + 2 * d] = bh[d];
    }
    __syncthreads();
#pragma unroll
    for (int i = 0; i < 4; i++) {
        const int r = ty + i * 8;       // local d
        const int d = d0 + r;
        g_B[(size_t)d * KB + k0 + tx]             = __float2half_rn(tile[0][tx][r]);
        g_B[(size_t)(512 + 2 * d) * KB + k0 + tx] = __float2half_rn(tile[1][tx][r]);
        g_B[(size_t)(513 + 2 * d) * KB + k0 + tx] = __float2half_rn(tile[2][tx][r]);
    }
}

// ---------------------------------------------------------------------------
// HMMA GEMM + fused activation epilogue (fp16 outputs).
// CTA 128x128, warp 32x64, KC=64 chunks, 3-stage cp.async pipeline.
// Fully-unrolled chunk loop (stage indices compile-time).  [R11 — frozen]
// grid = (NG/TN, MM/TM), block = 256
// ---------------------------------------------------------------------------
__global__ __launch_bounds__(256, 2) void gemm_tc()
{
    extern __shared__ __align__(128) char smem_raw[];
    const uint32_t sbase = smem_u32(smem_raw);

    const int tid  = threadIdx.x;
    const int lane = tid & 31;
    const int wid  = tid >> 5;
    const int wm   = wid >> 1;            // 0..3  (m)
    const int wn   = wid & 1;             // 0..1  (n)
    const int m0 = blockIdx.y * TM;
    const int n0 = blockIdx.x * TN;

    const int quad = lane >> 3;
    const int lrow = lane & 7;

    const __half* gA = g_A + (size_t)m0 * KA;
    const __half* gB = g_B + (size_t)n0 * KB;

    auto load_chunk = [&](int c, int s) {
        const uint32_t aB = sbase + (uint32_t)s * 32768u;
        const uint32_t bB = aB + 16384u;
        const int koff = c * KC;
#pragma unroll
        for (int j = 0; j < 4; j++) {
            const int flat = tid + j * 256;       // 0..1023
            const int r  = flat >> 3;             // row 0..127
            const int sg = flat & 7;              // 16B segment 0..7
            const uint32_t sw = ((uint32_t)(sg ^ (r & 7))) << 4;
            cpasync16(aB + (uint32_t)r * 128u + sw, gA + (size_t)r * KA + koff + sg * 8);
            cpasync16(bB + (uint32_t)r * 128u + sw, gB + (size_t)r * KB + koff + sg * 8);
        }
        asm volatile("cp.async.commit_group;" ::: "memory");
    };

    float acc[2][8][4];
#pragma unroll
    for (int i = 0; i < 2; i++)
#pragma unroll
        for (int j = 0; j < 8; j++)
#pragma unroll
            for (int q = 0; q < 4; q++) acc[i][j][q] = 0.0f;

    load_chunk(0, 0);
    load_chunk(1, 1);

#pragma unroll
    for (int c = 0; c < NCH; c++) {
        const int s = c % 3;
        asm volatile("cp.async.wait_group 1;" ::: "memory");
        __syncthreads();
        if (c + 2 < NCH) load_chunk(c + 2, (c + 2) % 3);
        else             asm volatile("cp.async.commit_group;" ::: "memory");

        const uint32_t aB = sbase + (uint32_t)s * 32768u;
        const uint32_t bB = aB + 16384u;

#pragma unroll
        for (int ks = 0; ks < 4; ks++) {
            uint32_t afr[2][4];
#pragma unroll
            for (int mt = 0; mt < 2; mt++) {
                const int row = wm * 32 + mt * 16 + (quad & 1) * 8 + lrow;
                const int seg = (ks * 2) + (quad >> 1);
                const uint32_t addr = aB + (uint32_t)row * 128u +
                                      ((uint32_t)(seg ^ (row & 7)) << 4);
                ldsm4(addr, afr[mt][0], afr[mt][1], afr[mt][2], afr[mt][3]);
            }
            uint32_t bfr[8][2];
#pragma unroll
            for (int np = 0; np < 4; np++) {
                const int nrow = wn * 64 + np * 16 + (quad >> 1) * 8 + lrow;
                const int seg = (ks * 2) + (quad & 1);
                const uint32_t addr = bB + (uint32_t)nrow * 128u +
                                      ((uint32_t)(seg ^ (nrow & 7)) << 4);
                ldsm4(addr, bfr[np * 2][0], bfr[np * 2][1],
                            bfr[np * 2 + 1][0], bfr[np * 2 + 1][1]);
            }
#pragma unroll
            for (int mt = 0; mt < 2; mt++)
#pragma unroll
                for (int nt = 0; nt < 8; nt++)
                    mma16816(acc[mt][nt], afr[mt], bfr[nt]);
        }
    }
    __syncthreads();

    if (n0 < 512) {
        // F gate: f = sigmoid(k + b), store half2 pairs
#pragma unroll
        for (int mt = 0; mt < 2; mt++) {
            const int mr = m0 + wm * 32 + mt * 16 + (lane >> 2);
#pragma unroll
            for (int nt = 0; nt < 8; nt++) {
                const int n = n0 + wn * 64 + nt * 8 + (lane & 3) * 2;
                const float bx = __ldg(&g_bias[n]);
                const float by = __ldg(&g_bias[n + 1]);
                __half2 p0 = __floats2half2_rn(sigmoidf_(acc[mt][nt][0] + bx),
                                               sigmoidf_(acc[mt][nt][1] + by));
                __half2 p1 = __floats2half2_rn(sigmoidf_(acc[mt][nt][2] + bx),
                                               sigmoidf_(acc[mt][nt][3] + by));
                *(__half2*)(g_f + (size_t)mr * DD + n)       = p0;
                *(__half2*)(g_f + (size_t)(mr + 8) * DD + n) = p1;
            }
        }
    } else {
        // I/H interleaved: fragment cols (2j, 2j+1) = (I_d, H_d)
        // v = sigmoid(kI + bI) * g(kH + bH). Stage fp32 in smem, store fp16.
        float* vbuf = (float*)smem_raw;     // [128][68] floats = 34816 B
        const int dloc_base = wn * 32;
#pragma unroll
        for (int mt = 0; mt < 2; mt++) {
            const int rloc = wm * 32 + mt * 16 + (lane >> 2);
#pragma unroll
            for (int nt = 0; nt < 8; nt++) {
                const int n = n0 + wn * 64 + nt * 8 + (lane & 3) * 2;
                const float bi_ = __ldg(&g_bias[n]);
                const float bh_ = __ldg(&g_bias[n + 1]);
                const int dloc = dloc_base + nt * 4 + (lane & 3);
                vbuf[rloc * 68 + dloc] =
                    sigmoidf_(acc[mt][nt][0] + bi_) * gfun_(acc[mt][nt][1] + bh_);
                vbuf[(rloc + 8) * 68 + dloc] =
                    sigmoidf_(acc[mt][nt][2] + bi_) * gfun_(acc[mt][nt][3] + bh_);
            }
        }
        __syncthreads();
        const int dbase = (n0 - 512) >> 1;   // global d of local col 0
#pragma unroll
        for (int j = 0; j < 8; j++) {
            const int flat = tid + j * 256;  // 0..2047 float4 units
            const int r  = flat >> 4;        // row 0..127
            const int f4 = flat & 15;        // 0..15
            float4 val = *(float4*)(vbuf + r * 68 + f4 * 4);
            __half2 h01 = __floats2half2_rn(val.x, val.y);
            __half2 h23 = __floats2half2_rn(val.z, val.w);
            uint2 pk;
            pk.x = *(uint32_t*)&h01;
            pk.y = *(uint32_t*)&h23;
            *(uint2*)(g_v + (size_t)(m0 + r) * DD + dbase + f4 * 4) = pk;
        }
    }
}

// ---------------------------------------------------------------------------
// Scan pass 1: per-chunk affine reduction, batched loads (MLP 16).
// grid=(NCHUNK, BB*2), block=128 — each block does 256 channels (half of d).
// ---------------------------------------------------------------------------
__global__ __launch_bounds__(128) void scan_chunks_kernel()
{
    const int c = blockIdx.x;
    const int b = blockIdx.y >> 1;
    const int dh = (blockIdx.y & 1) * 128;       // half2-unit offset
    const int t = dh + threadIdx.x;              // 0..255 half2 units
    const __half2* F = (const __half2*)g_f;
    const __half2* V = (const __half2*)g_v;
    size_t idx = (size_t)(b * SS + c * LCHUNK) * (DD / 2) + t;
    float2 A = {1.0f, 1.0f}, C = {0.0f, 0.0f};
#pragma unroll 1
    for (int g = 0; g < LCHUNK / SGRP; g++) {
        __half2 fb[SGRP], vb[SGRP];
#pragma unroll
        for (int j = 0; j < SGRP; j++) {
            fb[j] = F[idx + j * (DD / 2)];
            vb[j] = V[idx + j * (DD / 2)];
        }
#pragma unroll
        for (int j = 0; j < SGRP; j++) {
            float2 f = __half22float2(fb[j]);
            float2 v = __half22float2(vb[j]);
            A.x *= f.x;  A.y *= f.y;
            C.x = fmaf(f.x, C.x, v.x);
            C.y = fmaf(f.y, C.y, v.y);
        }
        idx += SGRP * (DD / 2);
    }
    const int o = (b * NCHUNK + c) * DD + 2 * t;
    *(float2*)(g_chA + o) = A;
    *(float2*)(g_chC + o) = C;
}

// ---------------------------------------------------------------------------
// Scan pass 2: serial carry, latency-hidden via group double-buffering.
// grid=BB, block=256
// ---------------------------------------------------------------------------
__global__ __launch_bounds__(256) void scan_carry_kernel(const float* __restrict__ pre_h)
{
    const int b = blockIdx.x, t = threadIdx.x;
    float2 h;
    h.x = gfun_(pre_h[b * DD + 2 * t]);
    h.y = gfun_(pre_h[b * DD + 2 * t + 1]);

    const int base = b * NCHUNK * DD + 2 * t;   // element offset of chunk 0

    float2 Abuf[2][CGRP], Cbuf[2][CGRP];
#pragma unroll
    for (int j = 0; j < CGRP; j++) {
        Abuf[0][j] = *(const float2*)(g_chA + base + j * DD);
        Cbuf[0][j] = *(const float2*)(g_chC + base + j * DD);
    }

#pragma unroll 1
    for (int g = 0; g < NCHUNK / CGRP; g++) {
        const int cur = g & 1, nxt = cur ^ 1;
        if (g + 1 < NCHUNK / CGRP) {
            const int nb = base + (g + 1) * CGRP * DD;
#pragma unroll
            for (int j = 0; j < CGRP; j++) {
                Abuf[nxt][j] = *(const float2*)(g_chA + nb + j * DD);
                Cbuf[nxt][j] = *(const float2*)(g_chC + nb + j * DD);
            }
        }
        const int cb = base + g * CGRP * DD;
#pragma unroll
        for (int j = 0; j < CGRP; j++) {
            *(float2*)(g_hin + cb + j * DD) = h;
            h.x = fmaf(Abuf[cur][j].x, h.x, Cbuf[cur][j].x);
            h.y = fmaf(Abuf[cur][j].y, h.y, Cbuf[cur][j].y);
        }
    }
}

// ---------------------------------------------------------------------------
// Scan pass 3: replay chunks with batched loads, write fp32 output.
// grid=(NCHUNK, BB*2), block=128
// ---------------------------------------------------------------------------
__global__ __launch_bounds__(128) void scan_apply_kernel(float* __restrict__ out)
{
    const int c = blockIdx.x;
    const int b = blockIdx.y >> 1;
    const int dh = (blockIdx.y & 1) * 128;
    const int t = dh + threadIdx.x;
    const __half2* F = (const __half2*)g_f;
    const __half2* V = (const __half2*)g_v;
    float2 h = *(const float2*)(g_hin + (b * NCHUNK + c) * DD + 2 * t);
    size_t idx = (size_t)(b * SS + c * LCHUNK) * (DD / 2) + t;
#pragma unroll 1
    for (int g = 0; g < LCHUNK / SGRP; g++) {
        __half2 fb[SGRP], vb[SGRP];
#pragma unroll
        for (int j = 0; j < SGRP; j++) {
            fb[j] = F[idx + j * (DD / 2)];
            vb[j] = V[idx + j * (DD / 2)];
        }
#pragma unroll
        for (int j = 0; j < SGRP; j++) {
            float2 f = __half22float2(fb[j]);
            float2 v = __half22float2(vb[j]);
            h.x = fmaf(f.x, h.x, v.x);
            h.y = fmaf(f.y, h.y, v.y);
            *(float2*)(out + (idx + j * (DD / 2)) * 2) = h;
        }
        idx += SGRP * (DD / 2);
    }
}

// ---------------------------------------------------------------------------
extern "C" void kernel_launch(void* const* d_in, const int* in_sizes, int n_in,
                              void* d_out, int out_size)
{
    const float* x     = (const float*)d_in[0];
    const float* pre_h = (const float*)d_in[1];
    const float* Wf    = (const float*)d_in[2];
    const float* bf    = (const float*)d_in[3];
    const float* Wi    = (const float*)d_in[4];
    const float* bi    = (const float*)d_in[5];
    const float* Wh    = (const float*)d_in[6];
    const float* bh    = (const float*)d_in[7];
    float* out = (float*)d_out;

    static bool attr_set = false;
    if (!attr_set) {
        cudaFuncSetAttribute(gemm_tc, cudaFuncAttributeMaxDynamicSharedMemorySize,
                             NSTAGE * 32768);
        attr_set = true;
    }

    prep_A<<<(MM * DD) / (256 * 8), 256>>>(x);
    prep_Bt<<<dim3(16, 16), dim3(32, 8)>>>(Wf, Wi, Wh, bf, bi, bh);

    gemm_tc<<<dim3(NG / TN, MM / TM), 256, NSTAGE * 32768>>>();

    scan_chunks_kernel<<<dim3(NCHUNK, BB * 2), 128>>>();
    scan_carry_kernel<<<BB, 256>>>(pre_h);
    scan_apply_kernel<<<dim3(NCHUNK, BB * 2), 128>>>(out);
}